// round 1
// baseline (speedup 1.0000x reference)
#include <cuda_runtime.h>

#define NQ     10
#define CDEPTH 6
#define NCLS   16
#define CBATCH 65536

// Precomputed cos/sin of half-angles for the 60 RY gates (params are batch-invariant).
__device__ float g_c[64];
__device__ float g_s[64];

__global__ void precompute_gates(const float* __restrict__ params) {
    int t = threadIdx.x;
    if (t < CDEPTH * NQ) {
        float s, c;
        sincosf(0.5f * params[t], &s, &c);
        g_c[t] = c;
        g_s[t] = s;
    }
}

// ---- packed f32x2 helpers (Blackwell sm_103a) ----
static __device__ __forceinline__ unsigned long long pk2(float lo, float hi) {
    unsigned long long r;
    asm("mov.b64 %0, {%1, %2};" : "=l"(r) : "f"(lo), "f"(hi));
    return r;
}
static __device__ __forceinline__ float2 upk2(unsigned long long v) {
    float2 r;
    asm("mov.b64 {%0, %1}, %2;" : "=f"(r.x), "=f"(r.y) : "l"(v));
    return r;
}
static __device__ __forceinline__ unsigned long long mul2(unsigned long long a, unsigned long long b) {
    unsigned long long r;
    asm("mul.rn.f32x2 %0, %1, %2;" : "=l"(r) : "l"(a), "l"(b));
    return r;
}
static __device__ __forceinline__ unsigned long long fma2(unsigned long long a, unsigned long long b,
                                                          unsigned long long c) {
    unsigned long long r;
    asm("fma.rn.f32x2 %0, %1, %2, %3;" : "=l"(r) : "l"(a), "l"(b), "l"(c));
    return r;
}

// One warp simulates one batch element. State: 1024 complex amps = 32 packed
// (re,im) f32x2 registers per lane. Amp index i = (lane<<5)|j; wire q <-> bit 9-q.
// Wires 0..4 live in lane bits (shfl gates), wires 5..9 in register bits (local pairs).
__global__ void __launch_bounds__(256, 2) qsim_kernel(
    const float* __restrict__ x,
    const float* __restrict__ w_cls,
    const float* __restrict__ b_cls,
    float* __restrict__ out)
{
    const int lane = threadIdx.x & 31;
    const int warp = threadIdx.x >> 5;
    const int e    = blockIdx.x * 8 + warp;

    // ---------- RX data-encoding layer: direct product-state construction ----------
    // amp(i) = (prod_q m_q) * (-i)^popcount(i),  m_q = cos(x_q/2) if bit==0 else sin(x_q/2)
    float myc = 1.f, mys = 0.f;
    if (lane < NQ) {
        sincosf(0.5f * x[e * NQ + lane], &mys, &myc);
    }
    float cc[NQ], sn[NQ];
    #pragma unroll
    for (int q = 0; q < NQ; q++) {
        cc[q] = __shfl_sync(0xFFFFFFFFu, myc, q);
        sn[q] = __shfl_sync(0xFFFFFFFFu, mys, q);
    }

    float L = 1.f;                       // product over lane-resident wires 0..4
    #pragma unroll
    for (int q = 0; q < 5; q++)
        L *= ((lane >> (4 - q)) & 1) ? sn[q] : cc[q];
    const int tl = __popc(lane);         // lane contribution to popcount

    unsigned long long a[32];
    #pragma unroll
    for (int j = 0; j < 32; j++) {
        float P = L;
        #pragma unroll
        for (int q = 5; q < NQ; q++)
            P *= ((j >> (9 - q)) & 1) ? sn[q] : cc[q];
        int tot = (tl + __popc(j)) & 3;  // phase (-i)^pc
        float re = (tot == 0) ? P : ((tot == 2) ? -P : 0.f);
        float im = (tot == 3) ? P : ((tot == 1) ? -P : 0.f);
        a[j] = pk2(re, im);
    }

    // ---------- CZ sign masks (identical every layer; pure sign-bit XOR) ----------
    // sign(i) = parity of {adjacent bit pairs (p+1,p) both == 1}, pairs p=0..8.
    const unsigned long long NEG2 = 0x8000000080000000ULL;
    const int plane = __popc(lane & (lane >> 1)) & 1;            // lane-internal pairs
    const unsigned long long MA = plane ? NEG2 : 0ULL;           // j bit4 == 0
    const unsigned long long MB = (plane ^ (lane & 1)) ? NEG2 : 0ULL; // j bit4 == 1 (cross pair 5,4)

    // ---------- 6 layers of RY (per-wire) + CZ chain ----------
    for (int d = 0; d < CDEPTH; ++d) {
        const float* gc = g_c + d * NQ;
        const float* gs = g_s + d * NQ;

        // lane-bit wires 0..4: exchange partner amp, new = c*mine + (bit? s : -s)*other
        #pragma unroll
        for (int q = 0; q < 5; q++) {
            const float c = gc[q], s = gs[q];
            const int   bit  = (lane >> (4 - q)) & 1;
            const int   dist = 1 << (4 - q);
            const unsigned long long c2  = pk2(c, c);
            const float sv = bit ? s : -s;
            const unsigned long long sv2 = pk2(sv, sv);
            #pragma unroll
            for (int j = 0; j < 32; j++) {
                unsigned long long o = __shfl_xor_sync(0xFFFFFFFFu, a[j], dist);
                a[j] = fma2(c2, a[j], mul2(sv2, o));
            }
        }

        // register-bit wires 5..9: in-place Givens rotation on pairs (j, j|2^p)
        #pragma unroll
        for (int q = 5; q < NQ; q++) {
            const float c = gc[q], s = gs[q];
            const unsigned long long c2  = pk2(c, c);
            const unsigned long long s2  = pk2(s, s);
            const unsigned long long ns2 = pk2(-s, -s);
            const int p = 9 - q;
            #pragma unroll
            for (int j = 0; j < 32; j++) {
                if (j & (1 << p)) continue;
                const int j1 = j | (1 << p);
                unsigned long long A0 = a[j], A1 = a[j1];
                a[j]  = fma2(c2, A0, mul2(ns2, A1));  // n0 = c*a0 - s*a1
                a[j1] = fma2(c2, A1, mul2(s2, A0));   // n1 = s*a0 + c*a1
            }
        }

        // CZ chain — skip after the last layer (probs are sign-invariant)
        if (d != CDEPTH - 1) {
            #pragma unroll
            for (int j = 0; j < 32; j++) {
                unsigned long long m = (j & 16) ? MB : MA;
                if (__popc(j & (j >> 1) & 0xF) & 1) m ^= NEG2;   // folds at compile time
                a[j] ^= m;
            }
        }
    }

    // ---------- probabilities and Z-expectations ----------
    float tot = 0.f, b0 = 0.f, b1 = 0.f, b2 = 0.f, b3 = 0.f, b4 = 0.f;
    #pragma unroll
    for (int j = 0; j < 32; j++) {
        float2 v = upk2(a[j]);
        float p = v.x * v.x + v.y * v.y;
        tot += p;
        b0 += (j & 1)  ? -p : p;   // local bit 0 -> wire 9
        b1 += (j & 2)  ? -p : p;   // wire 8
        b2 += (j & 4)  ? -p : p;   // wire 7
        b3 += (j & 8)  ? -p : p;   // wire 6
        b4 += (j & 16) ? -p : p;   // wire 5
    }
    // plain butterfly reduce the 5 local-wire sums
    #pragma unroll
    for (int st = 1; st < 32; st <<= 1) {
        b0 += __shfl_xor_sync(0xFFFFFFFFu, b0, st);
        b1 += __shfl_xor_sync(0xFFFFFFFFu, b1, st);
        b2 += __shfl_xor_sync(0xFFFFFFFFu, b2, st);
        b3 += __shfl_xor_sync(0xFFFFFFFFu, b3, st);
        b4 += __shfl_xor_sync(0xFFFFFFFFu, b4, st);
    }
    // lane-wire expectations: signed stage at the wire's lane bit, plain stages elsewhere
    float E[NQ];
    #pragma unroll
    for (int k = 0; k < 5; k++) {
        float g = tot;
        float o = __shfl_xor_sync(0xFFFFFFFFu, g, 1 << k);
        g = ((lane >> k) & 1) ? (o - g) : (g - o);
        #pragma unroll
        for (int st = 1; st < 32; st <<= 1) {
            if (st != (1 << k)) g += __shfl_xor_sync(0xFFFFFFFFu, g, st);
        }
        E[4 - k] = g;    // lane bit k <-> wire 4-k
    }
    E[5] = b4; E[6] = b3; E[7] = b2; E[8] = b1; E[9] = b0;

    // ---------- linear head: 16 classes, one per lane ----------
    if (lane < NCLS) {
        float acc = b_cls[lane];
        #pragma unroll
        for (int q = 0; q < NQ; q++)
            acc += E[q] * w_cls[lane * NQ + q];
        out[e * NCLS + lane] = acc;
    }
}

extern "C" void kernel_launch(void* const* d_in, const int* in_sizes, int n_in,
                              void* d_out, int out_size) {
    const float* x      = (const float*)d_in[0];
    const float* params = (const float*)d_in[1];
    const float* w_cls  = (const float*)d_in[2];
    const float* b_cls  = (const float*)d_in[3];
    float* out = (float*)d_out;

    precompute_gates<<<1, 64>>>(params);
    qsim_kernel<<<CBATCH / 8, 256>>>(x, w_cls, b_cls, out);
}

// round 7
// speedup vs baseline: 1.1870x; 1.1870x over previous
#include <cuda_runtime.h>

#define NQ     10
#define CDEPTH 6
#define NCLS   16
#define CBATCH 65536

// Precomputed cos/sin of half-angles for the 60 RY gates (params are batch-invariant).
__device__ float g_c[64];
__device__ float g_s[64];

__global__ void precompute_gates(const float* __restrict__ params) {
    int t = threadIdx.x;
    if (t < CDEPTH * NQ) {
        float s, c;
        sincosf(0.5f * params[t], &s, &c);
        g_c[t] = c;
        g_s[t] = s;
    }
}

// ---- packed f32x2 helpers (Blackwell sm_103a) ----
static __device__ __forceinline__ unsigned long long pk2(float lo, float hi) {
    unsigned long long r;
    asm("mov.b64 %0, {%1, %2};" : "=l"(r) : "f"(lo), "f"(hi));
    return r;
}
static __device__ __forceinline__ float2 upk2(unsigned long long v) {
    float2 r;
    asm("mov.b64 {%0, %1}, %2;" : "=f"(r.x), "=f"(r.y) : "l"(v));
    return r;
}
static __device__ __forceinline__ unsigned long long mul2(unsigned long long a, unsigned long long b) {
    unsigned long long r;
    asm("mul.rn.f32x2 %0, %1, %2;" : "=l"(r) : "l"(a), "l"(b));
    return r;
}
static __device__ __forceinline__ unsigned long long fma2(unsigned long long a, unsigned long long b,
                                                          unsigned long long c) {
    unsigned long long r;
    asm("fma.rn.f32x2 %0, %1, %2, %3;" : "=l"(r) : "l"(a), "l"(b), "l"(c));
    return r;
}

// One warp simulates one batch element. State: 1024 complex amps = 32 packed
// (re,im) f32x2 registers per lane. Amp index i = (lane<<5)|j; wire q <-> bit 9-q.
// Wires 0..4 live in lane bits (shfl gates), wires 5..9 in register bits (local pairs).
//
// Structure exploits:
//  - RX layer + first RY layer keep a product state -> built directly (no gates).
//  - Final CZ layer is sign-only -> invisible in probabilities -> skipped.
//  - Within a layer all 10 RYs commute -> lane-wire (SHFL-heavy) and reg-wire
//    (FMA-heavy) gates are fused per register pair so both pipes stay saturated.
__global__ void __launch_bounds__(256, 2) qsim_kernel(
    const float* __restrict__ x,
    const float* __restrict__ w_cls,
    const float* __restrict__ b_cls,
    float* __restrict__ out)
{
    const int lane = threadIdx.x & 31;
    const int warp = threadIdx.x >> 5;
    const int e    = blockIdx.x * 8 + warp;

    // ---------- init: RX(x) then RY(layer 0), still a product state ----------
    // per-wire 2-vector after RX then RY:
    //   v0 = (c*cx,  s*sx),  v1 = (s*cx, -c*sx)   [c,s = RY half-angle, cx,sx = RX half-angle]
    float v0r = 1.f, v0i = 0.f, v1r = 0.f, v1i = 0.f;
    if (lane < NQ) {
        float cx, sx;
        sincosf(0.5f * x[e * NQ + lane], &sx, &cx);
        float c = g_c[lane], s = g_s[lane];   // layer 0 gates
        v0r = c * cx;  v0i = s * sx;
        v1r = s * cx;  v1i = -c * sx;
    }
    float w0r[NQ], w0i[NQ], w1r[NQ], w1i[NQ];
    #pragma unroll
    for (int q = 0; q < NQ; q++) {
        w0r[q] = __shfl_sync(0xFFFFFFFFu, v0r, q);
        w0i[q] = __shfl_sync(0xFFFFFFFFu, v0i, q);
        w1r[q] = __shfl_sync(0xFFFFFFFFu, v1r, q);
        w1i[q] = __shfl_sync(0xFFFFFFFFu, v1i, q);
    }

    // lane-resident complex product over wires 0..4 (lane bit 4-q <-> wire q)
    float Lr, Li;
    {
        int b0 = (lane >> 4) & 1;
        Lr = b0 ? w1r[0] : w0r[0];
        Li = b0 ? w1i[0] : w0i[0];
        #pragma unroll
        for (int q = 1; q < 5; q++) {
            int b = (lane >> (4 - q)) & 1;
            float br = b ? w1r[q] : w0r[q];
            float bi = b ? w1i[q] : w0i[q];
            float nr = fmaf(-Li, bi, Lr * br);
            float ni = fmaf( Li, br, Lr * bi);
            Lr = nr; Li = ni;
        }
    }

    // product tree over wires 5..9 (j bit 9-q <-> wire q), rooted at L
    float tr[32], ti[32];
    tr[0] = Lr; ti[0] = Li;
    #pragma unroll
    for (int q = 5; q < NQ; q++) {
        const int m = 1 << (q - 5);      // current level size
        #pragma unroll
        for (int k = m - 1; k >= 0; k--) {
            float ar = tr[k], ai = ti[k];
            tr[2 * k + 1] = fmaf(-ai, w1i[q], ar * w1r[q]);
            ti[2 * k + 1] = fmaf( ai, w1r[q], ar * w1i[q]);
            tr[2 * k]     = fmaf(-ai, w0i[q], ar * w0r[q]);
            ti[2 * k]     = fmaf( ai, w0r[q], ar * w0i[q]);
        }
    }
    unsigned long long a[32];
    #pragma unroll
    for (int j = 0; j < 32; j++) a[j] = pk2(tr[j], ti[j]);

    // ---------- CZ sign masks (identical every layer; pure sign-bit XOR) ----------
    const unsigned long long NEG2 = 0x8000000080000000ULL;
    const int plane = __popc(lane & (lane >> 1)) & 1;                 // lane-internal pairs
    const unsigned long long MA = plane ? NEG2 : 0ULL;                // j bit4 == 0
    const unsigned long long MB = (plane ^ (lane & 1)) ? NEG2 : 0ULL; // j bit4 == 1 (cross pair 5,4)

    // CZ of layer 0 (the RY part was folded into the init)
    #pragma unroll
    for (int j = 0; j < 32; j++) {
        unsigned long long m = (j & 16) ? MB : MA;
        if (__popc(j & (j >> 1) & 0xF) & 1) m ^= NEG2;   // folds at compile time
        a[j] ^= m;
    }

    // ---------- layers 1..5: fused lane-wire(q) + reg-wire(q+5) gates ----------
    for (int d = 1; d < CDEPTH; ++d) {
        const float* gc = g_c + d * NQ;
        const float* gs = g_s + d * NQ;

        #pragma unroll
        for (int q = 0; q < 5; q++) {
            // lane wire q: new = c*mine + (bit ? s : -s)*partner
            const float cl = gc[q], sl = gs[q];
            const int   bit  = (lane >> (4 - q)) & 1;
            const int   dist = 1 << (4 - q);
            const unsigned long long c2l = pk2(cl, cl);
            const float sv = bit ? sl : -sl;
            const unsigned long long sv2 = pk2(sv, sv);
            // reg wire q+5: Givens on pairs (j, j | 1<<p), p = 4-q
            const float cr = gc[q + 5], sr = gs[q + 5];
            const unsigned long long c2r  = pk2(cr, cr);
            const unsigned long long s2r  = pk2(sr, sr);
            const unsigned long long ns2r = pk2(-sr, -sr);
            const int p = 4 - q;

            #pragma unroll
            for (int j = 0; j < 32; j++) {
                if (j & (1 << p)) continue;
                const int j1 = j | (1 << p);
                // issue both shuffles first; c*a is shfl-independent
                unsigned long long o0 = __shfl_xor_sync(0xFFFFFFFFu, a[j],  dist);
                unsigned long long o1 = __shfl_xor_sync(0xFFFFFFFFu, a[j1], dist);
                unsigned long long t0 = mul2(c2l, a[j]);
                unsigned long long t1 = mul2(c2l, a[j1]);
                unsigned long long A0 = fma2(sv2, o0, t0);   // lane gate applied
                unsigned long long A1 = fma2(sv2, o1, t1);
                a[j]  = fma2(c2r, A0, mul2(ns2r, A1));       // reg gate: n0 = c*a0 - s*a1
                a[j1] = fma2(c2r, A1, mul2(s2r,  A0));       //           n1 = s*a0 + c*a1
            }
        }

        // CZ chain -- skip after the last layer (probs are sign-invariant)
        if (d != CDEPTH - 1) {
            #pragma unroll
            for (int j = 0; j < 32; j++) {
                unsigned long long m = (j & 16) ? MB : MA;
                if (__popc(j & (j >> 1) & 0xF) & 1) m ^= NEG2;
                a[j] ^= m;
            }
        }
    }

    // ---------- probabilities and Z-expectations ----------
    float tot = 0.f, b0 = 0.f, b1 = 0.f, b2 = 0.f, b3 = 0.f, b4 = 0.f;
    #pragma unroll
    for (int j = 0; j < 32; j++) {
        float2 v = upk2(a[j]);
        float p = v.x * v.x + v.y * v.y;
        tot += p;
        b0 += (j & 1)  ? -p : p;   // local bit 0 -> wire 9
        b1 += (j & 2)  ? -p : p;   // wire 8
        b2 += (j & 4)  ? -p : p;   // wire 7
        b3 += (j & 8)  ? -p : p;   // wire 6
        b4 += (j & 16) ? -p : p;   // wire 5
    }
    #pragma unroll
    for (int st = 1; st < 32; st <<= 1) {
        b0 += __shfl_xor_sync(0xFFFFFFFFu, b0, st);
        b1 += __shfl_xor_sync(0xFFFFFFFFu, b1, st);
        b2 += __shfl_xor_sync(0xFFFFFFFFu, b2, st);
        b3 += __shfl_xor_sync(0xFFFFFFFFu, b3, st);
        b4 += __shfl_xor_sync(0xFFFFFFFFu, b4, st);
    }
    // lane-wire expectations: signed stage at the wire's lane bit, plain stages elsewhere
    float E[NQ];
    #pragma unroll
    for (int k = 0; k < 5; k++) {
        float g = tot;
        float o = __shfl_xor_sync(0xFFFFFFFFu, g, 1 << k);
        g = ((lane >> k) & 1) ? (o - g) : (g - o);
        #pragma unroll
        for (int st = 1; st < 32; st <<= 1) {
            if (st != (1 << k)) g += __shfl_xor_sync(0xFFFFFFFFu, g, st);
        }
        E[4 - k] = g;    // lane bit k <-> wire 4-k
    }
    E[5] = b4; E[6] = b3; E[7] = b2; E[8] = b1; E[9] = b0;

    // ---------- linear head: 16 classes, one per lane ----------
    if (lane < NCLS) {
        float acc = b_cls[lane];
        #pragma unroll
        for (int q = 0; q < NQ; q++)
            acc += E[q] * w_cls[lane * NQ + q];
        out[e * NCLS + lane] = acc;
    }
}

extern "C" void kernel_launch(void* const* d_in, const int* in_sizes, int n_in,
                              void* d_out, int out_size) {
    const float* x      = (const float*)d_in[0];
    const float* params = (const float*)d_in[1];
    const float* w_cls  = (const float*)d_in[2];
    const float* b_cls  = (const float*)d_in[3];
    float* out = (float*)d_out;

    precompute_gates<<<1, 64>>>(params);
    qsim_kernel<<<CBATCH / 8, 256>>>(x, w_cls, b_cls, out);
}

// round 9
// speedup vs baseline: 1.1973x; 1.0086x over previous
#include <cuda_runtime.h>

#define NQ     10
#define CDEPTH 6
#define NCLS   16
#define CBATCH 65536

// Precomputed cos/sin of half-angles for the 60 RY gates (params are batch-invariant).
__device__ float g_c[64];
__device__ float g_s[64];

__global__ void precompute_gates(const float* __restrict__ params) {
    int t = threadIdx.x;
    if (t < CDEPTH * NQ) {
        float s, c;
        sincosf(0.5f * params[t], &s, &c);
        g_c[t] = c;
        g_s[t] = s;
    }
}

// ---- packed f32x2 helpers (Blackwell sm_103a) ----
static __device__ __forceinline__ unsigned long long pk2(float lo, float hi) {
    unsigned long long r;
    asm("mov.b64 %0, {%1, %2};" : "=l"(r) : "f"(lo), "f"(hi));
    return r;
}
static __device__ __forceinline__ float2 upk2(unsigned long long v) {
    float2 r;
    asm("mov.b64 {%0, %1}, %2;" : "=f"(r.x), "=f"(r.y) : "l"(v));
    return r;
}
static __device__ __forceinline__ unsigned long long swap2(unsigned long long v) {
    float2 t = upk2(v);
    return pk2(t.y, t.x);
}
static __device__ __forceinline__ unsigned long long mul2(unsigned long long a, unsigned long long b) {
    unsigned long long r;
    asm("mul.rn.f32x2 %0, %1, %2;" : "=l"(r) : "l"(a), "l"(b));
    return r;
}
static __device__ __forceinline__ unsigned long long fma2(unsigned long long a, unsigned long long b,
                                                          unsigned long long c) {
    unsigned long long r;
    asm("fma.rn.f32x2 %0, %1, %2, %3;" : "=l"(r) : "l"(a), "l"(b), "l"(c));
    return r;
}

// One warp simulates one batch element. All gates after the (folded) init are
// REAL, so re/im evolve independently -- the component index is a passive bit.
//
// Bit layout (flat amp index bit 9-q <-> wire q):
//   lane bit 4..1 : wires 0..3   (SHFL gates, dist 16/8/4/2)
//   lane bit 0    : re/im component (never gated; summed in measurement)
//   f32x2 pack bit: wire 4       (local half-swap gate)
//   reg bits 4..0 : wires 5..9   (local Givens pairs)
// => only 4 shuffled wires per layer instead of 5 (-20% SHFL).
__global__ void __launch_bounds__(256, 2) qsim_kernel(
    const float* __restrict__ x,
    const float* __restrict__ w_cls,
    const float* __restrict__ b_cls,
    float* __restrict__ out)
{
    const int lane = threadIdx.x & 31;
    const int warp = threadIdx.x >> 5;
    const int e    = blockIdx.x * 8 + warp;
    const int comp = lane & 1;            // 0 = re, 1 = im

    // ---------- init: RX(x) then RY(layer 0), still a product state ----------
    // per-wire 2-vector (bit=0, bit=1) after RX then RY(layer-0):
    //   v0 = (c*cx,  s*sx),  v1 = (s*cx, -c*sx)
    float v0r = 1.f, v0i = 0.f, v1r = 0.f, v1i = 0.f;
    if (lane < NQ) {
        float cx, sx;
        sincosf(0.5f * x[e * NQ + lane], &sx, &cx);
        float c = g_c[lane], s = g_s[lane];
        v0r = c * cx;  v0i = s * sx;
        v1r = s * cx;  v1i = -c * sx;
    }
    float w0r[NQ], w0i[NQ], w1r[NQ], w1i[NQ];
    #pragma unroll
    for (int q = 0; q < NQ; q++) {
        w0r[q] = __shfl_sync(0xFFFFFFFFu, v0r, q);
        w0i[q] = __shfl_sync(0xFFFFFFFFu, v0i, q);
        w1r[q] = __shfl_sync(0xFFFFFFFFu, v1r, q);
        w1i[q] = __shfl_sync(0xFFFFFFFFu, v1i, q);
    }

    // complex product over lane wires 0..3 (wire q <-> lane bit 4-q)
    float Lr, Li;
    {
        int b0 = (lane >> 4) & 1;
        Lr = b0 ? w1r[0] : w0r[0];
        Li = b0 ? w1i[0] : w0i[0];
        #pragma unroll
        for (int q = 1; q < 4; q++) {
            int b = (lane >> (4 - q)) & 1;
            float br = b ? w1r[q] : w0r[q];
            float bi = b ? w1i[q] : w0i[q];
            float nr = fmaf(-Li, bi, Lr * br);
            float ni = fmaf( Li, br, Lr * bi);
            Lr = nr; Li = ni;
        }
    }

    // product tree over reg wires 5..9 (wire q <-> j bit 9-q), rooted at L
    float tr[32], ti[32];
    tr[0] = Lr; ti[0] = Li;
    #pragma unroll
    for (int q = 5; q < NQ; q++) {
        const int m = 1 << (q - 5);
        #pragma unroll
        for (int k = m - 1; k >= 0; k--) {
            float ar = tr[k], ai = ti[k];
            tr[2 * k + 1] = fmaf(-ai, w1i[q], ar * w1r[q]);
            ti[2 * k + 1] = fmaf( ai, w1r[q], ar * w1i[q]);
            tr[2 * k]     = fmaf(-ai, w0i[q], ar * w0r[q]);
            ti[2 * k]     = fmaf( ai, w0r[q], ar * w0i[q]);
        }
    }

    // fold in wire 4 (pack bit) and select component:
    //   lo = comp(P * v0(4)),  hi = comp(P * v1(4))
    const float al0 = comp ? w0i[4] :  w0r[4];
    const float be0 = comp ? w0r[4] : -w0i[4];
    const float al1 = comp ? w1i[4] :  w1r[4];
    const float be1 = comp ? w1r[4] : -w1i[4];
    unsigned long long a[32];
    #pragma unroll
    for (int j = 0; j < 32; j++) {
        float lo = fmaf(ti[j], be0, tr[j] * al0);
        float hi = fmaf(ti[j], be1, tr[j] * al1);
        a[j] = pk2(lo, hi);
    }

    // ---------- CZ sign masks ----------
    // BOTH negates both pack halves (sign independent of wire4); HI only bit4=1 half.
    const unsigned long long BOTH = 0x8000000080000000ULL;
    const unsigned long long HI   = 0x8000000000000000ULL;
    const int lw = (lane >> 1) & 0xF;                         // wires 0..3 as bits 3..0
    const int plane = __popc(lw & (lw >> 1)) & 1;             // pairs (0,1),(1,2),(2,3)
    const unsigned long long mlane =
        (plane ? BOTH : 0ULL) ^ (((lane >> 1) & 1) ? HI : 0ULL);  // + pair (3,4)

    // CZ of layer 0 (its RY part was folded into the init)
    #pragma unroll
    for (int j = 0; j < 32; j++) {
        unsigned long long mj = ((j & 16) ? HI : 0ULL)                      // pair (4,5)
                              ^ ((__popc(j & (j >> 1)) & 1) ? BOTH : 0ULL); // pairs (5..9)
        a[j] ^= mlane ^ mj;   // mj folds at compile time
    }

    // ---------- layers 1..5 ----------
    for (int d = 1; d < CDEPTH; ++d) {
        const float* gc = g_c + d * NQ;
        const float* gs = g_s + d * NQ;

        // fused: lane wire q (shfl) + reg wire 5+q (Givens on bit p = 4-q)
        #pragma unroll
        for (int q = 0; q < 4; q++) {
            const float cl = gc[q], sl = gs[q];
            const int   bit  = (lane >> (4 - q)) & 1;
            const int   dist = 1 << (4 - q);
            const unsigned long long c2l = pk2(cl, cl);
            const float sv = bit ? sl : -sl;
            const unsigned long long sv2 = pk2(sv, sv);
            const float cr = gc[q + 5], sr = gs[q + 5];
            const unsigned long long c2r  = pk2(cr, cr);
            const unsigned long long s2r  = pk2(sr, sr);
            const unsigned long long ns2r = pk2(-sr, -sr);
            const int p = 4 - q;

            #pragma unroll
            for (int j = 0; j < 32; j++) {
                if (j & (1 << p)) continue;
                const int j1 = j | (1 << p);
                unsigned long long o0 = __shfl_xor_sync(0xFFFFFFFFu, a[j],  dist);
                unsigned long long o1 = __shfl_xor_sync(0xFFFFFFFFu, a[j1], dist);
                unsigned long long t0 = mul2(c2l, a[j]);
                unsigned long long t1 = mul2(c2l, a[j1]);
                unsigned long long A0 = fma2(sv2, o0, t0);
                unsigned long long A1 = fma2(sv2, o1, t1);
                a[j]  = fma2(c2r, A0, mul2(ns2r, A1));
                a[j1] = fma2(c2r, A1, mul2(s2r,  A0));
            }
        }

        // tail: pack-bit wire 4 (half-swap) + reg wire 9 (Givens on bit 0)
        {
            const float c4 = gc[4], s4 = gs[4];
            const unsigned long long cp2 = pk2(c4, c4);
            const unsigned long long sp2 = pk2(-s4, s4);  // lo: -s*hi ; hi: +s*lo
            const float c9 = gc[9], s9 = gs[9];
            const unsigned long long c2r  = pk2(c9, c9);
            const unsigned long long s2r  = pk2(s9, s9);
            const unsigned long long ns2r = pk2(-s9, -s9);
            #pragma unroll
            for (int j = 0; j < 32; j += 2) {
                unsigned long long B0 = fma2(cp2, a[j],     mul2(sp2, swap2(a[j])));
                unsigned long long B1 = fma2(cp2, a[j + 1], mul2(sp2, swap2(a[j + 1])));
                a[j]     = fma2(c2r, B0, mul2(ns2r, B1));
                a[j + 1] = fma2(c2r, B1, mul2(s2r,  B0));
            }
        }

        // CZ chain -- skip after the last layer (probs are sign-invariant)
        if (d != CDEPTH - 1) {
            #pragma unroll
            for (int j = 0; j < 32; j++) {
                unsigned long long mj = ((j & 16) ? HI : 0ULL)
                                      ^ ((__popc(j & (j >> 1)) & 1) ? BOTH : 0ULL);
                a[j] ^= mlane ^ mj;
            }
        }
    }

    // ---------- probabilities and Z-expectations ----------
    // per reg: lo^2+hi^2 feeds tot & reg-wire Z's; lo^2-hi^2 feeds wire-4 Z.
    float tot = 0.f, z4 = 0.f, z5 = 0.f, z6 = 0.f, z7 = 0.f, z8 = 0.f, z9 = 0.f;
    #pragma unroll
    for (int j = 0; j < 32; j++) {
        float2 v = upk2(mul2(a[j], a[j]));
        float s = v.x + v.y;
        float dd = v.x - v.y;
        tot += s;  z4 += dd;
        z5 += (j & 16) ? -s : s;
        z6 += (j & 8)  ? -s : s;
        z7 += (j & 4)  ? -s : s;
        z8 += (j & 2)  ? -s : s;
        z9 += (j & 1)  ? -s : s;
    }
    // plain 5-stage butterflies (also sums out the component bit 0)
    #pragma unroll
    for (int st = 1; st < 32; st <<= 1) {
        z4 += __shfl_xor_sync(0xFFFFFFFFu, z4, st);
        z5 += __shfl_xor_sync(0xFFFFFFFFu, z5, st);
        z6 += __shfl_xor_sync(0xFFFFFFFFu, z6, st);
        z7 += __shfl_xor_sync(0xFFFFFFFFu, z7, st);
        z8 += __shfl_xor_sync(0xFFFFFFFFu, z8, st);
        z9 += __shfl_xor_sync(0xFFFFFFFFu, z9, st);
    }
    // lane wires 0..3: signed stage at lane bit m = 4-q, plain elsewhere
    float E[NQ];
    #pragma unroll
    for (int q = 0; q < 4; q++) {
        const int m = 4 - q;
        float g = tot;
        float o = __shfl_xor_sync(0xFFFFFFFFu, g, 1 << m);
        g = ((lane >> m) & 1) ? (o - g) : (g - o);
        #pragma unroll
        for (int st = 1; st < 32; st <<= 1) {
            if (st != (1 << m)) g += __shfl_xor_sync(0xFFFFFFFFu, g, st);
        }
        E[q] = g;
    }
    E[4] = z4; E[5] = z5; E[6] = z6; E[7] = z7; E[8] = z8; E[9] = z9;

    // ---------- linear head: 16 classes, one per lane ----------
    if (lane < NCLS) {
        float acc = b_cls[lane];
        #pragma unroll
        for (int q = 0; q < NQ; q++)
            acc += E[q] * w_cls[lane * NQ + q];
        out[e * NCLS + lane] = acc;
    }
}

extern "C" void kernel_launch(void* const* d_in, const int* in_sizes, int n_in,
                              void* d_out, int out_size) {
    const float* x      = (const float*)d_in[0];
    const float* params = (const float*)d_in[1];
    const float* w_cls  = (const float*)d_in[2];
    const float* b_cls  = (const float*)d_in[3];
    float* out = (float*)d_out;

    precompute_gates<<<1, 64>>>(params);
    qsim_kernel<<<CBATCH / 8, 256>>>(x, w_cls, b_cls, out);
}

// round 10
// speedup vs baseline: 1.5206x; 1.2700x over previous
#include <cuda_runtime.h>

#define NQ     10
#define CDEPTH 6
#define NCLS   16
#define CBATCH 65536

// Gate tables. Layers 1..5 use fast-Givens: t = tan(half-angle), with the
// global product of cosines folded into g_C2 (applied to expectations).
__device__ float g_c[64];
__device__ float g_s[64];
__device__ float g_t[64];
__device__ float g_C2;

__global__ void precompute_gates(const float* __restrict__ params) {
    __shared__ float cs[64];
    int t = threadIdx.x;
    if (t < CDEPTH * NQ) {
        float s, c;
        sincosf(0.5f * params[t], &s, &c);
        g_c[t] = c;
        g_s[t] = s;
        g_t[t] = s / c;
        cs[t] = c;
    }
    __syncthreads();
    if (t == 0) {
        float C = 1.f;
        for (int i = NQ; i < CDEPTH * NQ; i++) C *= cs[i];   // layers 1..5 only
        g_C2 = C * C;
    }
}

// ---- packed f32x2 helpers (Blackwell sm_103a) ----
static __device__ __forceinline__ unsigned long long pk2(float lo, float hi) {
    unsigned long long r;
    asm("mov.b64 %0, {%1, %2};" : "=l"(r) : "f"(lo), "f"(hi));
    return r;
}
static __device__ __forceinline__ float2 upk2(unsigned long long v) {
    float2 r;
    asm("mov.b64 {%0, %1}, %2;" : "=f"(r.x), "=f"(r.y) : "l"(v));
    return r;
}
static __device__ __forceinline__ unsigned long long swap2(unsigned long long v) {
    float2 t = upk2(v);
    return pk2(t.y, t.x);
}
static __device__ __forceinline__ unsigned long long mul2(unsigned long long a, unsigned long long b) {
    unsigned long long r;
    asm("mul.rn.f32x2 %0, %1, %2;" : "=l"(r) : "l"(a), "l"(b));
    return r;
}
static __device__ __forceinline__ unsigned long long fma2(unsigned long long a, unsigned long long b,
                                                          unsigned long long c) {
    unsigned long long r;
    asm("fma.rn.f32x2 %0, %1, %2, %3;" : "=l"(r) : "l"(a), "l"(b), "l"(c));
    return r;
}

// One warp per batch element; 1024 complex amps as 32 packed f32x2 per lane.
// Bit layout (flat amp index bit 9-q <-> wire q):
//   lane bits 4..1 : wires 0..3  (SHFL gates)
//   lane bit 0     : re/im component (passive)
//   pack bit       : wire 4      (local half-swap gate)
//   reg bits 4..0  : wires 5..9  (local Givens pairs)
// Layers 1..5 use fast-Givens (1 fma2 per amp per lane gate, 2 per reg pair);
// the factored-out cos product is applied as g_C2 to the expectations.
__global__ void __launch_bounds__(256, 2) qsim_kernel(
    const float* __restrict__ x,
    const float* __restrict__ w_cls,
    const float* __restrict__ b_cls,
    float* __restrict__ out)
{
    const int lane = threadIdx.x & 31;
    const int warp = threadIdx.x >> 5;
    const int e    = blockIdx.x * 8 + warp;
    const int comp = lane & 1;            // 0 = re, 1 = im

    // ---------- init: RX(x) then RY(layer 0) -- product state ----------
    float v0r = 1.f, v0i = 0.f, v1r = 0.f, v1i = 0.f;
    if (lane < NQ) {
        float cx, sx;
        sincosf(0.5f * x[e * NQ + lane], &sx, &cx);
        float c = g_c[lane], s = g_s[lane];
        v0r = c * cx;  v0i = s * sx;
        v1r = s * cx;  v1i = -c * sx;
    }
    float w0r[NQ], w0i[NQ], w1r[NQ], w1i[NQ];
    #pragma unroll
    for (int q = 0; q < NQ; q++) {
        w0r[q] = __shfl_sync(0xFFFFFFFFu, v0r, q);
        w0i[q] = __shfl_sync(0xFFFFFFFFu, v0i, q);
        w1r[q] = __shfl_sync(0xFFFFFFFFu, v1r, q);
        w1i[q] = __shfl_sync(0xFFFFFFFFu, v1i, q);
    }

    // complex product over lane wires 0..3 (wire q <-> lane bit 4-q)
    float Lr, Li;
    {
        int b0 = (lane >> 4) & 1;
        Lr = b0 ? w1r[0] : w0r[0];
        Li = b0 ? w1i[0] : w0i[0];
        #pragma unroll
        for (int q = 1; q < 4; q++) {
            int b = (lane >> (4 - q)) & 1;
            float br = b ? w1r[q] : w0r[q];
            float bi = b ? w1i[q] : w0i[q];
            float nr = fmaf(-Li, bi, Lr * br);
            float ni = fmaf( Li, br, Lr * bi);
            Lr = nr; Li = ni;
        }
    }

    // product tree over reg wires 5..9, rooted at L
    float tr[32], ti[32];
    tr[0] = Lr; ti[0] = Li;
    #pragma unroll
    for (int q = 5; q < NQ; q++) {
        const int m = 1 << (q - 5);
        #pragma unroll
        for (int k = m - 1; k >= 0; k--) {
            float ar = tr[k], ai = ti[k];
            tr[2 * k + 1] = fmaf(-ai, w1i[q], ar * w1r[q]);
            ti[2 * k + 1] = fmaf( ai, w1r[q], ar * w1i[q]);
            tr[2 * k]     = fmaf(-ai, w0i[q], ar * w0r[q]);
            ti[2 * k]     = fmaf( ai, w0r[q], ar * w0i[q]);
        }
    }

    // fold in wire 4 (pack bit), select component
    const float al0 = comp ? w0i[4] :  w0r[4];
    const float be0 = comp ? w0r[4] : -w0i[4];
    const float al1 = comp ? w1i[4] :  w1r[4];
    const float be1 = comp ? w1r[4] : -w1i[4];
    unsigned long long a[32];
    #pragma unroll
    for (int j = 0; j < 32; j++) {
        float lo = fmaf(ti[j], be0, tr[j] * al0);
        float hi = fmaf(ti[j], be1, tr[j] * al1);
        a[j] = pk2(lo, hi);
    }

    // ---------- CZ sign masks ----------
    const unsigned long long BOTH = 0x8000000080000000ULL;
    const unsigned long long HI   = 0x8000000000000000ULL;
    const int lw = (lane >> 1) & 0xF;
    const int plane = __popc(lw & (lw >> 1)) & 1;
    const unsigned long long mlane =
        (plane ? BOTH : 0ULL) ^ (((lane >> 1) & 1) ? HI : 0ULL);

    // CZ of layer 0
    #pragma unroll
    for (int j = 0; j < 32; j++) {
        unsigned long long mj = ((j & 16) ? HI : 0ULL)
                              ^ ((__popc(j & (j >> 1)) & 1) ? BOTH : 0ULL);
        a[j] ^= mlane ^ mj;
    }

    // ---------- layers 1..5: fast-Givens gates ----------
    for (int d = 1; d < CDEPTH; ++d) {
        const float* gt = g_t + d * NQ;

        // fused: lane wire q (shfl, 1 fma2/amp) + reg wire 5+q (2 fma2/pair)
        #pragma unroll
        for (int q = 0; q < 4; q++) {
            const float tl = gt[q];
            const int   bit  = (lane >> (4 - q)) & 1;
            const int   dist = 1 << (4 - q);
            const float tv = bit ? tl : -tl;
            const unsigned long long tv2 = pk2(tv, tv);
            const float trg = gt[q + 5];
            const unsigned long long trp = pk2(trg, trg);
            const unsigned long long trn = pk2(-trg, -trg);
            const int p = 4 - q;

            #pragma unroll
            for (int j = 0; j < 32; j++) {
                if (j & (1 << p)) continue;
                const int j1 = j | (1 << p);
                unsigned long long o0 = __shfl_xor_sync(0xFFFFFFFFu, a[j],  dist);
                unsigned long long o1 = __shfl_xor_sync(0xFFFFFFFFu, a[j1], dist);
                unsigned long long A0 = fma2(tv2, o0, a[j]);    // lane gate (scaled)
                unsigned long long A1 = fma2(tv2, o1, a[j1]);
                a[j]  = fma2(trn, A1, A0);                      // reg gate (scaled)
                a[j1] = fma2(trp, A0, A1);
            }
        }

        // tail: pack-bit wire 4 (half-swap) + reg wire 9 (bit 0)
        {
            const float t4 = gt[4];
            const unsigned long long sp = pk2(-t4, t4);   // lo: -t*hi ; hi: +t*lo
            const float t9 = gt[9];
            const unsigned long long t9p = pk2(t9, t9);
            const unsigned long long t9n = pk2(-t9, -t9);
            #pragma unroll
            for (int j = 0; j < 32; j += 2) {
                unsigned long long B0 = fma2(sp, swap2(a[j]),     a[j]);
                unsigned long long B1 = fma2(sp, swap2(a[j + 1]), a[j + 1]);
                a[j]     = fma2(t9n, B1, B0);
                a[j + 1] = fma2(t9p, B0, B1);
            }
        }

        // CZ chain -- skip after the last layer
        if (d != CDEPTH - 1) {
            #pragma unroll
            for (int j = 0; j < 32; j++) {
                unsigned long long mj = ((j & 16) ? HI : 0ULL)
                                      ^ ((__popc(j & (j >> 1)) & 1) ? BOTH : 0ULL);
                a[j] ^= mlane ^ mj;
            }
        }
    }

    // ---------- probabilities and Z-expectations (raw scale; *C2 later) ----------
    float tot = 0.f, z4 = 0.f, z5 = 0.f, z6 = 0.f, z7 = 0.f, z8 = 0.f, z9 = 0.f;
    #pragma unroll
    for (int j = 0; j < 32; j++) {
        float2 v = upk2(mul2(a[j], a[j]));
        float s = v.x + v.y;
        float dd = v.x - v.y;
        tot += s;  z4 += dd;
        z5 += (j & 16) ? -s : s;
        z6 += (j & 8)  ? -s : s;
        z7 += (j & 4)  ? -s : s;
        z8 += (j & 2)  ? -s : s;
        z9 += (j & 1)  ? -s : s;
    }
    #pragma unroll
    for (int st = 1; st < 32; st <<= 1) {
        z4 += __shfl_xor_sync(0xFFFFFFFFu, z4, st);
        z5 += __shfl_xor_sync(0xFFFFFFFFu, z5, st);
        z6 += __shfl_xor_sync(0xFFFFFFFFu, z6, st);
        z7 += __shfl_xor_sync(0xFFFFFFFFu, z7, st);
        z8 += __shfl_xor_sync(0xFFFFFFFFu, z8, st);
        z9 += __shfl_xor_sync(0xFFFFFFFFu, z9, st);
    }
    float E[NQ];
    #pragma unroll
    for (int q = 0; q < 4; q++) {
        const int m = 4 - q;
        float g = tot;
        float o = __shfl_xor_sync(0xFFFFFFFFu, g, 1 << m);
        g = ((lane >> m) & 1) ? (o - g) : (g - o);
        #pragma unroll
        for (int st = 1; st < 32; st <<= 1) {
            if (st != (1 << m)) g += __shfl_xor_sync(0xFFFFFFFFu, g, st);
        }
        E[q] = g;
    }
    E[4] = z4; E[5] = z5; E[6] = z6; E[7] = z7; E[8] = z8; E[9] = z9;

    // restore the factored-out cos^2 product
    const float C2 = g_C2;
    #pragma unroll
    for (int q = 0; q < NQ; q++) E[q] *= C2;

    // ---------- linear head ----------
    if (lane < NCLS) {
        float acc = b_cls[lane];
        #pragma unroll
        for (int q = 0; q < NQ; q++)
            acc += E[q] * w_cls[lane * NQ + q];
        out[e * NCLS + lane] = acc;
    }
}

extern "C" void kernel_launch(void* const* d_in, const int* in_sizes, int n_in,
                              void* d_out, int out_size) {
    const float* x      = (const float*)d_in[0];
    const float* params = (const float*)d_in[1];
    const float* w_cls  = (const float*)d_in[2];
    const float* b_cls  = (const float*)d_in[3];
    float* out = (float*)d_out;

    precompute_gates<<<1, 64>>>(params);
    qsim_kernel<<<CBATCH / 8, 256>>>(x, w_cls, b_cls, out);
}

// round 15
// speedup vs baseline: 1.6221x; 1.0668x over previous
#include <cuda_runtime.h>

#define NQ     10
#define CDEPTH 6
#define NCLS   16
#define CBATCH 65536

// Gate tables. Layers 1..5 use fast-Givens: t = tan(half-angle), with the
// global product of cosines folded into g_C2 (applied to expectations).
__device__ float g_c[64];
__device__ float g_s[64];
__device__ float g_t[64];
__device__ float g_C2;

__global__ void precompute_gates(const float* __restrict__ params) {
    __shared__ float cs[64];
    int t = threadIdx.x;
    if (t < CDEPTH * NQ) {
        float s, c;
        sincosf(0.5f * params[t], &s, &c);
        g_c[t] = c;
        g_s[t] = s;
        g_t[t] = s / c;
        cs[t] = c;
    }
    __syncthreads();
    if (t == 0) {
        float C = 1.f;
        for (int i = NQ; i < CDEPTH * NQ; i++) C *= cs[i];   // layers 1..5 only
        g_C2 = C * C;
    }
}

// ---- packed f32x2 helpers (Blackwell sm_103a) ----
static __device__ __forceinline__ unsigned long long pk2(float lo, float hi) {
    unsigned long long r;
    asm("mov.b64 %0, {%1, %2};" : "=l"(r) : "f"(lo), "f"(hi));
    return r;
}
static __device__ __forceinline__ float2 upk2(unsigned long long v) {
    float2 r;
    asm("mov.b64 {%0, %1}, %2;" : "=f"(r.x), "=f"(r.y) : "l"(v));
    return r;
}
static __device__ __forceinline__ unsigned long long swap2(unsigned long long v) {
    float2 t = upk2(v);
    return pk2(t.y, t.x);
}
static __device__ __forceinline__ unsigned long long mul2(unsigned long long a, unsigned long long b) {
    unsigned long long r;
    asm("mul.rn.f32x2 %0, %1, %2;" : "=l"(r) : "l"(a), "l"(b));
    return r;
}
static __device__ __forceinline__ unsigned long long fma2(unsigned long long a, unsigned long long b,
                                                          unsigned long long c) {
    unsigned long long r;
    asm("fma.rn.f32x2 %0, %1, %2, %3;" : "=l"(r) : "l"(a), "l"(b), "l"(c));
    return r;
}

// One warp per batch element; 1024 complex amps as 32 packed f32x2 per lane.
// Bit layout (flat amp index bit 9-q <-> wire q):
//   lane bits 4..1 : wires 0..3  (SHFL gates)
//   lane bit 0     : re/im component (passive)
//   pack bit       : wire 4      (local half-swap gate)
//   reg bits 4..0  : wires 5..9  (local Givens pairs)
// Layers 1..5 use fast-Givens; the cos product is restored via g_C2 at the end.
// Init builds the complex product tree IN-PLACE in a[] (packed re,im) so the
// register peak stays ~80 -> 3 CTAs/SM (launch_bounds caps regs at 85).
__global__ void __launch_bounds__(256, 3) qsim_kernel(
    const float* __restrict__ x,
    const float* __restrict__ w_cls,
    const float* __restrict__ b_cls,
    float* __restrict__ out)
{
    const int lane = threadIdx.x & 31;
    const int warp = threadIdx.x >> 5;
    const int e    = blockIdx.x * 8 + warp;
    const int comp = lane & 1;            // 0 = re, 1 = im

    // ---------- init: RX(x) then RY(layer 0) -- product state ----------
    // per-wire 2-vector (bit=0, bit=1): v0 = (c*cx, s*sx), v1 = (s*cx, -c*sx)
    float v0r = 1.f, v0i = 0.f, v1r = 0.f, v1i = 0.f;
    if (lane < NQ) {
        float cx, sx;
        sincosf(0.5f * x[e * NQ + lane], &sx, &cx);
        float c = g_c[lane], s = g_s[lane];
        v0r = c * cx;  v0i = s * sx;
        v1r = s * cx;  v1i = -c * sx;
    }

    // lane-resident complex product over lane wires 0..3 (wire q <-> lane bit 4-q)
    // broadcasts consumed one wire at a time (4 floats live, not 40)
    float Lr, Li;
    {
        float b0r = __shfl_sync(0xFFFFFFFFu, v0r, 0);
        float b0i = __shfl_sync(0xFFFFFFFFu, v0i, 0);
        float b1r = __shfl_sync(0xFFFFFFFFu, v1r, 0);
        float b1i = __shfl_sync(0xFFFFFFFFu, v1i, 0);
        int b = (lane >> 4) & 1;
        Lr = b ? b1r : b0r;
        Li = b ? b1i : b0i;
        #pragma unroll
        for (int q = 1; q < 4; q++) {
            b0r = __shfl_sync(0xFFFFFFFFu, v0r, q);
            b0i = __shfl_sync(0xFFFFFFFFu, v0i, q);
            b1r = __shfl_sync(0xFFFFFFFFu, v1r, q);
            b1i = __shfl_sync(0xFFFFFFFFu, v1i, q);
            int bb = (lane >> (4 - q)) & 1;
            float br = bb ? b1r : b0r;
            float bi = bb ? b1i : b0i;
            float nr = fmaf(-Li, bi, Lr * br);
            float ni = fmaf( Li, br, Lr * bi);
            Lr = nr; Li = ni;
        }
    }

    // in-place complex product tree over reg wires 5..9, a[k] = packed (re,im)
    unsigned long long a[32];
    a[0] = pk2(Lr, Li);
    #pragma unroll
    for (int q = 5; q < NQ; q++) {
        const float c0r = __shfl_sync(0xFFFFFFFFu, v0r, q);
        const float c0i = __shfl_sync(0xFFFFFFFFu, v0i, q);
        const float c1r = __shfl_sync(0xFFFFFFFFu, v1r, q);
        const float c1i = __shfl_sync(0xFFFFFFFFu, v1i, q);
        const unsigned long long W0a = pk2(c0r, c0r);
        const unsigned long long W0b = pk2(-c0i, c0i);
        const unsigned long long W1a = pk2(c1r, c1r);
        const unsigned long long W1b = pk2(-c1i, c1i);
        const int m = 1 << (q - 5);
        #pragma unroll
        for (int k = m - 1; k >= 0; k--) {        // descending k: write-safe
            unsigned long long p  = a[k];
            unsigned long long sp = swap2(p);     // (im, re)
            a[2 * k + 1] = fma2(W1a, p, mul2(W1b, sp));  // p * w1 (complex)
            a[2 * k]     = fma2(W0a, p, mul2(W0b, sp));  // p * w0 (complex)
        }
    }

    // wire-4 fold + component selection (local per j):
    //   lo = al0*re + be0*im,  hi = al1*re + be1*im
    {
        const float c0r = __shfl_sync(0xFFFFFFFFu, v0r, 4);
        const float c0i = __shfl_sync(0xFFFFFFFFu, v0i, 4);
        const float c1r = __shfl_sync(0xFFFFFFFFu, v1r, 4);
        const float c1i = __shfl_sync(0xFFFFFFFFu, v1i, 4);
        const float alLo = comp ? c0i : c0r;
        const float beLo = comp ? c0r : -c0i;
        const float alHi = comp ? c1i : c1r;
        const float beHi = comp ? c1r : -c1i;
        const unsigned long long AL = pk2(alLo, alHi);
        const unsigned long long BE = pk2(beLo, beHi);
        #pragma unroll
        for (int j = 0; j < 32; j++) {
            float2 v = upk2(a[j]);
            a[j] = fma2(AL, pk2(v.x, v.x), mul2(BE, pk2(v.y, v.y)));
        }
    }

    // ---------- CZ sign masks ----------
    const unsigned long long BOTH = 0x8000000080000000ULL;
    const unsigned long long HI   = 0x8000000000000000ULL;
    const int lw = (lane >> 1) & 0xF;
    const int plane = __popc(lw & (lw >> 1)) & 1;
    const unsigned long long mlane =
        (plane ? BOTH : 0ULL) ^ (((lane >> 1) & 1) ? HI : 0ULL);

    // CZ of layer 0
    #pragma unroll
    for (int j = 0; j < 32; j++) {
        unsigned long long mj = ((j & 16) ? HI : 0ULL)
                              ^ ((__popc(j & (j >> 1)) & 1) ? BOTH : 0ULL);
        a[j] ^= mlane ^ mj;
    }

    // ---------- layers 1..5: fast-Givens gates ----------
    for (int d = 1; d < CDEPTH; ++d) {
        const float* gt = g_t + d * NQ;

        // fused: lane wire q (shfl, 1 fma2/amp) + reg wire 5+q (2 fma2/pair)
        #pragma unroll
        for (int q = 0; q < 4; q++) {
            const float tl = gt[q];
            const int   bit  = (lane >> (4 - q)) & 1;
            const int   dist = 1 << (4 - q);
            const float tv = bit ? tl : -tl;
            const unsigned long long tv2 = pk2(tv, tv);
            const float trg = gt[q + 5];
            const unsigned long long trp = pk2(trg, trg);
            const unsigned long long trn = trp ^ BOTH;   // negated via sign XOR
            const int p = 4 - q;

            #pragma unroll
            for (int j = 0; j < 32; j++) {
                if (j & (1 << p)) continue;
                const int j1 = j | (1 << p);
                unsigned long long o0 = __shfl_xor_sync(0xFFFFFFFFu, a[j],  dist);
                unsigned long long o1 = __shfl_xor_sync(0xFFFFFFFFu, a[j1], dist);
                unsigned long long A0 = fma2(tv2, o0, a[j]);    // lane gate (scaled)
                unsigned long long A1 = fma2(tv2, o1, a[j1]);
                a[j]  = fma2(trn, A1, A0);                      // reg gate (scaled)
                a[j1] = fma2(trp, A0, A1);
            }
        }

        // tail: pack-bit wire 4 (half-swap) + reg wire 9 (bit 0)
        {
            const float t4 = gt[4];
            const unsigned long long sp = pk2(-t4, t4);   // lo: -t*hi ; hi: +t*lo
            const float t9 = gt[9];
            const unsigned long long t9p = pk2(t9, t9);
            const unsigned long long t9n = t9p ^ BOTH;
            #pragma unroll
            for (int j = 0; j < 32; j += 2) {
                unsigned long long B0 = fma2(sp, swap2(a[j]),     a[j]);
                unsigned long long B1 = fma2(sp, swap2(a[j + 1]), a[j + 1]);
                a[j]     = fma2(t9n, B1, B0);
                a[j + 1] = fma2(t9p, B0, B1);
            }
        }

        // CZ chain -- skip after the last layer
        if (d != CDEPTH - 1) {
            #pragma unroll
            for (int j = 0; j < 32; j++) {
                unsigned long long mj = ((j & 16) ? HI : 0ULL)
                                      ^ ((__popc(j & (j >> 1)) & 1) ? BOTH : 0ULL);
                a[j] ^= mlane ^ mj;
            }
        }
    }

    // ---------- probabilities and Z-expectations (raw scale; *C2 later) ----------
    float tot = 0.f, z4 = 0.f, z5 = 0.f, z6 = 0.f, z7 = 0.f, z8 = 0.f, z9 = 0.f;
    #pragma unroll
    for (int j = 0; j < 32; j++) {
        float2 v = upk2(mul2(a[j], a[j]));
        float s = v.x + v.y;
        float dd = v.x - v.y;
        tot += s;  z4 += dd;
        z5 += (j & 16) ? -s : s;
        z6 += (j & 8)  ? -s : s;
        z7 += (j & 4)  ? -s : s;
        z8 += (j & 2)  ? -s : s;
        z9 += (j & 1)  ? -s : s;
    }
    #pragma unroll
    for (int st = 1; st < 32; st <<= 1) {
        z4 += __shfl_xor_sync(0xFFFFFFFFu, z4, st);
        z5 += __shfl_xor_sync(0xFFFFFFFFu, z5, st);
        z6 += __shfl_xor_sync(0xFFFFFFFFu, z6, st);
        z7 += __shfl_xor_sync(0xFFFFFFFFu, z7, st);
        z8 += __shfl_xor_sync(0xFFFFFFFFu, z8, st);
        z9 += __shfl_xor_sync(0xFFFFFFFFu, z9, st);
    }
    float E[NQ];
    #pragma unroll
    for (int q = 0; q < 4; q++) {
        const int m = 4 - q;
        float g = tot;
        float o = __shfl_xor_sync(0xFFFFFFFFu, g, 1 << m);
        g = ((lane >> m) & 1) ? (o - g) : (g - o);
        #pragma unroll
        for (int st = 1; st < 32; st <<= 1) {
            if (st != (1 << m)) g += __shfl_xor_sync(0xFFFFFFFFu, g, st);
        }
        E[q] = g;
    }
    E[4] = z4; E[5] = z5; E[6] = z6; E[7] = z7; E[8] = z8; E[9] = z9;

    // restore the factored-out cos^2 product
    const float C2 = g_C2;
    #pragma unroll
    for (int q = 0; q < NQ; q++) E[q] *= C2;

    // ---------- linear head ----------
    if (lane < NCLS) {
        float acc = b_cls[lane];
        #pragma unroll
        for (int q = 0; q < NQ; q++)
            acc += E[q] * w_cls[lane * NQ + q];
        out[e * NCLS + lane] = acc;
    }
}

extern "C" void kernel_launch(void* const* d_in, const int* in_sizes, int n_in,
                              void* d_out, int out_size) {
    const float* x      = (const float*)d_in[0];
    const float* params = (const float*)d_in[1];
    const float* w_cls  = (const float*)d_in[2];
    const float* b_cls  = (const float*)d_in[3];
    float* out = (float*)d_out;

    precompute_gates<<<1, 64>>>(params);
    qsim_kernel<<<CBATCH / 8, 256>>>(x, w_cls, b_cls, out);
}